// round 3
// baseline (speedup 1.0000x reference)
#include <cuda_runtime.h>
#include <math.h>

// ---------------- problem constants ----------------
#define NNODES 325
#define BATCH  64
#define TSTEPS 12
#define HORIZON 12
#define UNITS  64
#define DIN    2

#define NB (NNODES*BATCH)        // 20800 rows
#define F3MAX 384
#define MAXNNZ 110000            // >= N*N, cannot overflow

// ---------------- device scratch (no allocs allowed) ----------------
__device__ float g_h0[NB*UNITS];     // layer-0 hidden (enc then dec)
__device__ float g_h1[NB*UNITS];     // layer-1 hidden (enc then dec)
__device__ float g_din[NB];          // decoder input (DOUT=1)
__device__ float g_xk[NB*F3MAX];     // concat + diffusion workspace, row stride F3
__device__ float g_ru[NB*2*UNITS];   // gate outputs (only u half [64,128) used)
__device__ int   g_rowptr[NNODES+1];
__device__ int   g_cols[MAXNNZ];
__device__ float g_vals[MAXNNZ];
// padded CSR for S2 = 2*S@S  (x2 = S2 @ x0 - x0)
__device__ int   g_cnt2[NNODES];
__device__ int   g_cols2[NNODES*NNODES];
__device__ float g_vals2[NNODES*NNODES];

// ---------------- f32x2 packed-FMA helpers (sm_103a) ----------------
typedef unsigned long long ull;
__device__ __forceinline__ ull pk2(float x, float y){
    ull r; asm("mov.b64 %0,{%1,%2};" : "=l"(r) : "f"(x), "f"(y)); return r;
}
__device__ __forceinline__ void upk2(ull v, float &x, float &y){
    asm("mov.b64 {%0,%1},%2;" : "=f"(x), "=f"(y) : "l"(v));
}
__device__ __forceinline__ void fma2(ull &acc, ull a, ull b){
    asm("fma.rn.f32x2 %0,%1,%2,%0;" : "+l"(acc) : "l"(a), "l"(b));
}

// ---------------- CSR build (support is ~2% sparse; exact-zero skip) ----------------
__global__ void build_csr(const float* __restrict__ S){
    __shared__ int cnt[NNODES+1];
    int t = threadIdx.x;
    for (int r = t; r < NNODES; r += blockDim.x){
        int c = 0;
        for (int j = 0; j < NNODES; j++) c += (S[r*NNODES + j] != 0.0f);
        cnt[r] = c;
    }
    __syncthreads();
    if (t == 0){
        int acc = 0;
        for (int r = 0; r < NNODES; r++){ int c = cnt[r]; cnt[r] = acc; acc += c; }
        cnt[NNODES] = acc;
    }
    __syncthreads();
    for (int r = t; r <= NNODES; r += blockDim.x) g_rowptr[r] = cnt[r];
    for (int r = t; r < NNODES; r += blockDim.x){
        int p = cnt[r];
        for (int j = 0; j < NNODES; j++){
            float v = S[r*NNODES + j];
            if (v != 0.0f){ g_cols[p] = j; g_vals[p] = v; p++; }
        }
    }
}

// ---------------- S2 = 2*S@S, padded CSR (deterministic, no atomics) ----------------
__global__ void build_s2(const float* __restrict__ S){
    __shared__ float rowv[NNODES];
    int m = blockIdx.x;
    int p0 = g_rowptr[m], p1 = g_rowptr[m+1];
    for (int c = threadIdx.x; c < NNODES; c += blockDim.x){
        float acc = 0.f;
        for (int j = p0; j < p1; j++)
            acc += g_vals[j] * S[g_cols[j]*NNODES + c];
        rowv[c] = 2.f*acc;
    }
    __syncthreads();
    if (threadIdx.x == 0){
        int c2 = 0;
        for (int c = 0; c < NNODES; c++){
            float v = rowv[c];
            if (v != 0.f){ g_cols2[m*NNODES + c2] = c; g_vals2[m*NNODES + c2] = v; c2++; }
        }
        g_cnt2[m] = c2;
    }
}

// ---------------- zero initial state ----------------
__global__ void zero_state(){
    int i = blockIdx.x*blockDim.x + threadIdx.x;
    if (i < NB*UNITS){ g_h0[i] = 0.f; g_h1[i] = 0.f; }
    if (i < NB) g_din[i] = 0.f;
}

// ---------------- fused concat + Chebyshev diffusion ----------------
// phase 0 (gate): builds x0 = [x,h] on the fly from sources, writes x0 to g_xk,
//                 computes x1 = S x0 and x2 = S2 x0 - x0, writes to g_xk.
// phase 1 (cand): reads rh columns [Fx,F) of g_xk (written by gate epilogue),
//                 computes rh1 = S rh, rh2 = S2 rh - rh into the h-subcolumns of x1/x2.
// grid: (ceil(ncols/32), BATCH); block 256. One 32-col chunk of one batch lane,
// all 325 nodes staged in smem.
__global__ __launch_bounds__(256)
void gconv_fused(int phase, int xsel /*0:h0 1:din 2:inp*/, int Fx, int hsel,
                 const float* __restrict__ inp_t)
{
    __shared__ float s[NNODES][32];
    const int F = Fx + UNITS, F3 = 3*F;
    const int ncols = phase ? UNITS : F;
    const int b  = blockIdx.y;
    const int f0 = blockIdx.x*32;
    const int nf = min(32, ncols - f0);
    const int tid = threadIdx.x, lane = tid & 31, wid = tid >> 5;
    const float* H = hsel ? g_h1 : g_h0;

    // stage x0 (or rh) for all nodes, this batch lane, this 32-col chunk
    for (int idx = tid; idx < NNODES*32; idx += 256){
        int k = idx >> 5, f = idx & 31;
        int ff = f0 + f;
        float v = 0.f;
        if (f < nf){
            int rb = k*BATCH + b;
            if (phase){
                v = g_xk[rb*F3 + Fx + ff];
            } else {
                if (ff < Fx){
                    if (xsel == 2)      v = inp_t[b*(NNODES*DIN) + k*DIN + ff];
                    else if (xsel == 1) v = g_din[rb];
                    else                v = g_h0[rb*UNITS + ff];
                } else {
                    v = H[rb*UNITS + (ff - Fx)];
                }
                g_xk[rb*F3 + ff] = v;   // materialize x0 for the GEMM
            }
        }
        s[k][f] = v;
    }
    __syncthreads();

    const int woff = phase ? Fx : 0;
    for (int m = wid; m < NNODES; m += 8){
        float a1 = 0.f, a2 = 0.f;
        int p0 = g_rowptr[m], p1 = g_rowptr[m+1];
        #pragma unroll 4
        for (int j = p0; j < p1; j++)
            a1 += g_vals[j] * s[g_cols[j]][lane];
        int c2 = g_cnt2[m];
        const int*   cp = g_cols2 + m*NNODES;
        const float* vp = g_vals2 + m*NNODES;
        #pragma unroll 4
        for (int j = 0; j < c2; j++)
            a2 += vp[j] * s[cp[j]][lane];
        a2 -= s[m][lane];
        if (lane < nf){
            int orow = (m*BATCH + b)*F3;
            int ff = f0 + lane;
            g_xk[orow + F   + woff + ff] = a1;
            g_xk[orow + 2*F + woff + ff] = a2;
        }
    }
}

// ---------------- weight GEMM with fused GRU epilogues ----------------
// C = A(g_xk: NB x F3) @ W(F3 x ONUM) + bias
// epi 0 (gate, ONUM=128): s = sigmoid(v); cols<64: xk[row][Fx+col] = s*H (r*h)
//                                          cols>=64: g_ru[row][col] = s   (u)
// epi 1 (cand, ONUM=64):  c = tanh(v); H = u*H + (1-u)*c (in place)
// epi 2 (cand + projection): epi1 + out[b*N+n] = hnew @ pW + pb; also g_din
#define BM 128
#define BK 16

template<int ONUM>
__global__ __launch_bounds__(256)
void gemm_act(int F3, const float* __restrict__ W, const float* __restrict__ bias,
              int hsel, int epi, int Fx,
              const float* __restrict__ pW, const float* __restrict__ pb,
              float* __restrict__ out_t)
{
    const int NPT = ONUM/16;                 // cols per thread: 8 or 4
    __shared__ float As[BK][BM+4];
    __shared__ float Bs[BK][ONUM];
    float* H = hsel ? g_h1 : g_h0;

    int tid = threadIdx.x;
    int tx = tid & 15, ty = tid >> 4;
    int row0 = blockIdx.x*BM;

    ull acc[8][NPT/2];
    #pragma unroll
    for (int i = 0; i < 8; i++)
        #pragma unroll
        for (int j = 0; j < NPT/2; j++) acc[i][j] = 0ull;

    int ktiles = (F3 + BK - 1)/BK;
    for (int kt = 0; kt < ktiles; kt++){
        int k0 = kt*BK;
        #pragma unroll
        for (int l = 0; l < (BM*BK)/256; l++){
            int idx = l*256 + tid;
            int kk = idx & 15, mm = idx >> 4;
            int r = row0 + mm, k = k0 + kk;
            As[kk][mm] = (r < NB && k < F3) ? g_xk[r*F3 + k] : 0.f;
        }
        #pragma unroll
        for (int l = 0; l < (ONUM*BK)/256; l++){
            int idx = l*256 + tid;
            int n = idx % ONUM, kk = idx / ONUM;
            int k = k0 + kk;
            Bs[kk][n] = (k < F3) ? W[k*ONUM + n] : 0.f;
        }
        __syncthreads();
        #pragma unroll
        for (int kk = 0; kk < BK; kk++){
            float4 av0 = *(const float4*)&As[kk][ty*8];
            float4 av1 = *(const float4*)&As[kk][ty*8 + 4];
            float a8[8] = {av0.x, av0.y, av0.z, av0.w, av1.x, av1.y, av1.z, av1.w};
            ull b2[NPT/2];
            #pragma unroll
            for (int j = 0; j < NPT/4; j++){
                float4 bv = *(const float4*)&Bs[kk][tx*NPT + j*4];
                b2[2*j]   = pk2(bv.x, bv.y);
                b2[2*j+1] = pk2(bv.z, bv.w);
            }
            #pragma unroll
            for (int i = 0; i < 8; i++){
                ull aa = pk2(a8[i], a8[i]);
                #pragma unroll
                for (int j = 0; j < NPT/2; j++) fma2(acc[i][j], aa, b2[j]);
            }
        }
        __syncthreads();
    }

    #pragma unroll
    for (int i = 0; i < 8; i++){
        int r = row0 + ty*8 + i;
        bool valid = (r < NB);
        int rc = valid ? r : 0;       // clamp for safe loads; stores guarded
        float pv = 0.f;
        #pragma unroll
        for (int j = 0; j < NPT/2; j++){
            float v0, v1; upk2(acc[i][j], v0, v1);
            int n0 = tx*NPT + 2*j;
            v0 += bias[n0]; v1 += bias[n0+1];
            if (epi == 0){
                float s0 = 1.f/(1.f + expf(-v0));
                float s1 = 1.f/(1.f + expf(-v1));
                if (n0 < UNITS){   // r: write r*h into concat buffer for cand gconv
                    if (valid){
                        g_xk[rc*F3 + Fx + n0]     = s0 * H[rc*UNITS + n0];
                        g_xk[rc*F3 + Fx + n0 + 1] = s1 * H[rc*UNITS + n0 + 1];
                    }
                } else {           // u
                    if (valid){
                        g_ru[rc*(2*UNITS) + n0]     = s0;
                        g_ru[rc*(2*UNITS) + n0 + 1] = s1;
                    }
                }
            } else {
                float c0 = tanhf(v0), c1 = tanhf(v1);
                float u0 = g_ru[rc*(2*UNITS) + UNITS + n0];
                float u1 = g_ru[rc*(2*UNITS) + UNITS + n0 + 1];
                float h0v = H[rc*UNITS + n0], h1v = H[rc*UNITS + n0 + 1];
                float hn0 = u0*h0v + (1.f - u0)*c0;
                float hn1 = u1*h1v + (1.f - u1)*c1;
                if (valid){
                    H[rc*UNITS + n0]     = hn0;
                    H[rc*UNITS + n0 + 1] = hn1;
                }
                if (epi == 2)
                    pv += hn0*pW[n0] + hn1*pW[n0 + 1];
            }
        }
        if (epi == 2){
            // reduce across the 16 column-threads (same ty -> same row, 16-lane group)
            #pragma unroll
            for (int o = 8; o > 0; o >>= 1)
                pv += __shfl_xor_sync(0xffffffffu, pv, o);
            if (tx == 0 && valid){
                pv += pb[0];
                int n = rc / BATCH, bb = rc % BATCH;
                out_t[bb*NNODES + n] = pv;
                g_din[rc] = pv;
            }
        }
    }
}

// ---------------- host-side cell orchestration ----------------
static void launch_cell(const float* inp_t /*enc0 only, else null*/,
                        int xsel, int Fx, int hsel,
                        const float* gW, const float* gb,
                        const float* cW, const float* cb,
                        int cand_epi,
                        const float* pW, const float* pb, float* out_t)
{
    int F = Fx + UNITS, F3 = 3*F;
    int gchunks = (F + 31)/32;
    // gate gconv: concat + x1 + x2 in one kernel
    gconv_fused<<<dim3(gchunks, BATCH), 256>>>(0, xsel, Fx, hsel, inp_t);
    // gate GEMM: sigmoid; writes u to g_ru, r*h into xk h-columns
    gemm_act<2*UNITS><<<(NB + BM - 1)/BM, 256>>>(F3, gW, gb, hsel, 0, Fx,
                                                 nullptr, nullptr, nullptr);
    // cand gconv: only h-columns need re-diffusion (x-columns reused)
    gconv_fused<<<dim3(2, BATCH), 256>>>(1, xsel, Fx, hsel, nullptr);
    // cand GEMM: tanh + GRU combine (+ optional fused projection)
    gemm_act<UNITS><<<(NB + BM - 1)/BM, 256>>>(F3, cW, cb, hsel, cand_epi, Fx,
                                               pW, pb, out_t);
}

extern "C" void kernel_launch(void* const* d_in, const int* in_sizes, int n_in,
                              void* d_out, int out_size)
{
    const float* inputs  = (const float*)d_in[0];   // (T, B, N*DIN)
    const float* support = (const float*)d_in[1];   // (N, N)
    const float* e0gW = (const float*)d_in[2];  const float* e0gb = (const float*)d_in[3];
    const float* e0cW = (const float*)d_in[4];  const float* e0cb = (const float*)d_in[5];
    const float* e1gW = (const float*)d_in[6];  const float* e1gb = (const float*)d_in[7];
    const float* e1cW = (const float*)d_in[8];  const float* e1cb = (const float*)d_in[9];
    const float* d0gW = (const float*)d_in[10]; const float* d0gb = (const float*)d_in[11];
    const float* d0cW = (const float*)d_in[12]; const float* d0cb = (const float*)d_in[13];
    const float* d1gW = (const float*)d_in[14]; const float* d1gb = (const float*)d_in[15];
    const float* d1cW = (const float*)d_in[16]; const float* d1cb = (const float*)d_in[17];
    const float* pW   = (const float*)d_in[18]; const float* pb   = (const float*)d_in[19];
    float* out = (float*)d_out;                     // (HZ, B, N)

    build_csr<<<1, 352>>>(support);
    build_s2<<<NNODES, 325>>>(support);
    zero_state<<<(NB*UNITS + 255)/256, 256>>>();

    // ---- encoder ----
    for (int t = 0; t < TSTEPS; t++){
        const float* inp_t = inputs + (size_t)t * BATCH * NNODES * DIN;
        launch_cell(inp_t,  2, DIN,   0, e0gW, e0gb, e0cW, e0cb, 1, nullptr, nullptr, nullptr);
        launch_cell(nullptr,0, UNITS, 1, e1gW, e1gb, e1cW, e1cb, 1, nullptr, nullptr, nullptr);
    }

    // ---- decoder (g_din starts as GO = 0) ----
    for (int t = 0; t < HORIZON; t++){
        launch_cell(nullptr, 1, 1,     0, d0gW, d0gb, d0cW, d0cb, 1, nullptr, nullptr, nullptr);
        launch_cell(nullptr, 0, UNITS, 1, d1gW, d1gb, d1cW, d1cb, 2, pW, pb,
                    out + (size_t)t * BATCH * NNODES);
    }
}